// round 1
// baseline (speedup 1.0000x reference)
#include <cuda_runtime.h>
#include <cuda_bf16.h>
#include <math.h>

// Problem constants
#define BATCH      8192
#define INPUT_DIM  256
#define HIDDEN     64
#define NUM_INNER  255
#define NUM_LEAVES 256
#define DEPTH      8

// GEMM tiling
#define BM 128
#define BN 64
#define BK 32
#define TM 8
#define TN 4
// 256 threads: tm_idx = tid>>4 (16 row-groups of 8), tn_idx = tid&15 (16 col-groups of 4)

// ---------------------------------------------------------------------------
// Kernel 1: fused per-node MLP.
//   For node n, batch tile m0..m0+127:
//     h = relu(X_tile @ W1[n]^T + b1[n])   (128 x 64, kept in registers)
//     logit[b] = h[b,:] . w2[n] + b2[n]
//     node_out[b, n] = sigmoid(logit[b])
// ---------------------------------------------------------------------------
__global__ __launch_bounds__(256, 2)
void sdt_node_mlp_kernel(const float* __restrict__ x,
                         const float* __restrict__ w1,
                         const float* __restrict__ b1,
                         const float* __restrict__ w2,
                         const float* __restrict__ b2,
                         float* __restrict__ node_out /* [BATCH, 255] */) {
    const int node  = blockIdx.x;          // 0..254
    const int mbase = blockIdx.y * BM;     // batch tile offset

    __shared__ float As[BM][BK + 1];       // x tile, stride 33 (conflict-light)
    __shared__ float Bs[BN][BK + 1];       // w1 tile
    __shared__ float logits_s[BM];

    const int tid    = threadIdx.x;
    const int tm_idx = tid >> 4;           // 0..15 -> rows tm_idx*8 .. +7
    const int tn_idx = tid & 15;           // 0..15 -> cols tn_idx*4 .. +3

    if (tid < BM) logits_s[tid] = 0.0f;    // covered by first __syncthreads below

    float acc[TM][TN];
#pragma unroll
    for (int r = 0; r < TM; r++)
#pragma unroll
        for (int c = 0; c < TN; c++) acc[r][c] = 0.0f;

    const float* __restrict__ w1n = w1 + (size_t)node * HIDDEN * INPUT_DIM;

    for (int k0 = 0; k0 < INPUT_DIM; k0 += BK) {
        // Load X tile: 128 rows x 32 k = 1024 float4, 4 per thread (coalesced)
#pragma unroll
        for (int i = 0; i < 4; i++) {
            int e  = tid + i * 256;        // 0..1023
            int r  = e >> 3;               // row 0..127
            int kg = (e & 7) << 2;         // k offset 0,4,..,28
            float4 v = *(const float4*)(x + (size_t)(mbase + r) * INPUT_DIM + k0 + kg);
            As[r][kg + 0] = v.x; As[r][kg + 1] = v.y;
            As[r][kg + 2] = v.z; As[r][kg + 3] = v.w;
        }
        // Load W1 tile: 64 rows x 32 k = 512 float4, 2 per thread
#pragma unroll
        for (int i = 0; i < 2; i++) {
            int e  = tid + i * 256;        // 0..511
            int r  = e >> 3;               // row 0..63
            int kg = (e & 7) << 2;
            float4 v = *(const float4*)(w1n + (size_t)r * INPUT_DIM + k0 + kg);
            Bs[r][kg + 0] = v.x; Bs[r][kg + 1] = v.y;
            Bs[r][kg + 2] = v.z; Bs[r][kg + 3] = v.w;
        }
        __syncthreads();

#pragma unroll
        for (int k = 0; k < BK; k++) {
            float rm[TM], rn[TN];
#pragma unroll
            for (int r = 0; r < TM; r++) rm[r] = As[tm_idx * TM + r][k];
#pragma unroll
            for (int c = 0; c < TN; c++) rn[c] = Bs[tn_idx * TN + c][k];
#pragma unroll
            for (int r = 0; r < TM; r++)
#pragma unroll
                for (int c = 0; c < TN; c++)
                    acc[r][c] = fmaf(rm[r], rn[c], acc[r][c]);
        }
        __syncthreads();
    }

    // Epilogue: bias, relu, dot with w2, row-reduce across the 16 col-groups
    float w2v[TN], b1v[TN];
#pragma unroll
    for (int c = 0; c < TN; c++) {
        int col = tn_idx * TN + c;
        w2v[c] = w2[node * HIDDEN + col];
        b1v[c] = b1[node * HIDDEN + col];
    }
#pragma unroll
    for (int r = 0; r < TM; r++) {
        float part = 0.0f;
#pragma unroll
        for (int c = 0; c < TN; c++) {
            float h = acc[r][c] + b1v[c];
            h = fmaxf(h, 0.0f);
            part = fmaf(h, w2v[c], part);
        }
        atomicAdd(&logits_s[tm_idx * TM + r], part);
    }
    __syncthreads();

    if (tid < BM) {
        float lg = logits_s[tid] + b2[node];
        float s  = 1.0f / (1.0f + __expf(-lg));
        node_out[(size_t)(mbase + tid) * NUM_INNER + node] = s;
    }
}

// ---------------------------------------------------------------------------
// Kernel 2: tree traversal. One block (256 threads) per batch element.
//   thread t (= leaf index) computes path_probs[b][t] as the product of its
//   8 ancestor decisions; threads <255 also compute node_reach; block
//   reduction gives h_out = path_probs . leaf.
// ---------------------------------------------------------------------------
__global__ __launch_bounds__(256)
void sdt_tree_kernel(const float* __restrict__ node_out, /* [BATCH,255] */
                     const float* __restrict__ leaf,     /* [256] */
                     float* __restrict__ h_out,          /* [BATCH] */
                     float* __restrict__ path_out,       /* [BATCH,256] */
                     float* __restrict__ reach_out) {    /* [BATCH,255] */
    const int b = blockIdx.x;
    const int t = threadIdx.x;     // 0..255 = leaf index

    __shared__ float p[NUM_INNER];
    __shared__ float red[8];

    if (t < NUM_INNER) p[t] = node_out[(size_t)b * NUM_INNER + t];
    __syncthreads();

    // Leaf path probability: decisions are the bits of t, MSB first.
    float prob = 1.0f;
#pragma unroll
    for (int v = 0; v < DEPTH; v++) {
        int node = (1 << v) - 1 + (t >> (DEPTH - v));
        float pv = p[node];
        prob *= ((t >> (DEPTH - 1 - v)) & 1) ? pv : (1.0f - pv);
    }
    path_out[(size_t)b * NUM_LEAVES + t] = prob;

    // Node reach: product along the path from root to node t (exclusive).
    if (t < NUM_INNER) {
        int v = 31 - __clz(t + 1);        // level of node t
        int i = t + 1 - (1 << v);         // index within level
        float reach = 1.0f;
        for (int u = 0; u < v; u++) {
            int node = (1 << u) - 1 + (i >> (v - u));
            float pv = p[node];
            reach *= ((i >> (v - 1 - u)) & 1) ? pv : (1.0f - pv);
        }
        reach_out[(size_t)b * NUM_INNER + t] = reach;
    }

    // h_out = sum_l path[l] * leaf[l]
    float contrib = prob * leaf[t];
#pragma unroll
    for (int off = 16; off; off >>= 1)
        contrib += __shfl_xor_sync(0xffffffffu, contrib, off);
    if ((t & 31) == 0) red[t >> 5] = contrib;
    __syncthreads();
    if (t < 8) {
        float v2 = red[t];
#pragma unroll
        for (int off = 4; off; off >>= 1)
            v2 += __shfl_xor_sync(0xffu, v2, off);
        if (t == 0) h_out[b] = v2;
    }
}

// ---------------------------------------------------------------------------
// Launch. d_in order: x, w1, b1, w2, b2, leaf.
// d_out (float): [h_out | path_probs | node_outputs | node_reach]
// ---------------------------------------------------------------------------
extern "C" void kernel_launch(void* const* d_in, const int* in_sizes, int n_in,
                              void* d_out, int out_size) {
    const float* x    = (const float*)d_in[0];
    const float* w1   = (const float*)d_in[1];
    const float* b1   = (const float*)d_in[2];
    const float* w2   = (const float*)d_in[3];
    const float* b2   = (const float*)d_in[4];
    const float* leaf = (const float*)d_in[5];

    float* out       = (float*)d_out;
    float* h_out     = out;                                       // 8192
    float* path_out  = out + BATCH;                               // 8192*256
    float* node_out  = out + BATCH + (size_t)BATCH * NUM_LEAVES;  // 8192*255
    float* reach_out = node_out + (size_t)BATCH * NUM_INNER;      // 8192*255

    dim3 grid1(NUM_INNER, BATCH / BM);   // 255 x 64
    sdt_node_mlp_kernel<<<grid1, 256>>>(x, w1, b1, w2, b2, node_out);

    sdt_tree_kernel<<<BATCH, 256>>>(node_out, leaf, h_out, path_out, reach_out);
}

// round 3
// speedup vs baseline: 5.4429x; 5.4429x over previous
#include <cuda_runtime.h>
#include <cuda_bf16.h>
#include <math.h>
#include <stdint.h>

// Problem constants
#define BATCH      8192
#define INPUT_DIM  256
#define HIDDEN     64
#define NUM_INNER  255
#define NUM_LEAVES 256
#define DEPTH      8

#define NODES_PAD  256                    // pad to even tiling
#define NX   (BATCH * INPUT_DIM)          // 2,097,152
#define NW1  (NUM_INNER * HIDDEN * INPUT_DIM)   // 4,177,920
#define NW1P (NODES_PAD * HIDDEN * INPUT_DIM)   // 4,194,304

// GEMM tiling
#define BM 128
#define BN 256          // 4 nodes per CTA
#define BK 32           // k per stage (64 bytes per row in smem)
#define NSTAGES (INPUT_DIM / BK)   // 8

// bf16 hi/lo scratch (static device arrays; no allocation)
__device__ __nv_bfloat16 g_xh[NX];
__device__ __nv_bfloat16 g_xl[NX];
__device__ __nv_bfloat16 g_w1h[NW1P];
__device__ __nv_bfloat16 g_w1l[NW1P];

// ---------------------------------------------------------------------------
// Prep: split fp32 -> bf16 hi + bf16 lo. Also zero-pads w1 rows for node 255.
// ---------------------------------------------------------------------------
__global__ void sdt_prep_kernel(const float* __restrict__ x,
                                const float* __restrict__ w1) {
    int stride = gridDim.x * blockDim.x;
    for (int i = blockIdx.x * blockDim.x + threadIdx.x; i < NX; i += stride) {
        float v = x[i];
        __nv_bfloat16 h = __float2bfloat16_rn(v);
        g_xh[i] = h;
        g_xl[i] = __float2bfloat16_rn(v - __bfloat162float(h));
    }
    for (int i = blockIdx.x * blockDim.x + threadIdx.x; i < NW1P; i += stride) {
        float v = (i < NW1) ? w1[i] : 0.0f;
        __nv_bfloat16 h = __float2bfloat16_rn(v);
        g_w1h[i] = h;
        g_w1l[i] = __float2bfloat16_rn(v - __bfloat162float(h));
    }
}

// ---------------------------------------------------------------------------
// smem layout helpers (all offsets in bytes within extern shared)
//  per stage buffer (48KB): Ah(8K) Al(8K) Bh(16K) Bl(16K); 2 buffers = 96KB
// Rows are 64B (32 bf16); 16B chunks swizzled: stored chunk = c ^ ((row>>1)&3)
// ---------------------------------------------------------------------------
#define BUF_STRIDE 49152
#define OFF_AH 0
#define OFF_AL 8192
#define OFF_BH 16384
#define OFF_BL 32768

__device__ __forceinline__ void cp_async16(uint32_t saddr, const void* gaddr) {
    asm volatile("cp.async.cg.shared.global [%0], [%1], 16;\n"
                 :: "r"(saddr), "l"(gaddr) : "memory");
}
__device__ __forceinline__ void cp_commit() {
    asm volatile("cp.async.commit_group;\n" ::: "memory");
}
__device__ __forceinline__ void cp_wait1() {
    asm volatile("cp.async.wait_group 1;\n" ::: "memory");
}
__device__ __forceinline__ void ldsm_x4(uint32_t* r, uint32_t addr) {
    asm volatile("ldmatrix.sync.aligned.m8n8.x4.shared.b16 {%0,%1,%2,%3}, [%4];\n"
                 : "=r"(r[0]), "=r"(r[1]), "=r"(r[2]), "=r"(r[3])
                 : "r"(addr));
}
__device__ __forceinline__ void mma_bf16(float* c, const uint32_t* a, const uint32_t* b) {
    asm volatile(
        "mma.sync.aligned.m16n8k16.row.col.f32.bf16.bf16.f32 "
        "{%0,%1,%2,%3}, {%4,%5,%6,%7}, {%8,%9}, {%0,%1,%2,%3};\n"
        : "+f"(c[0]), "+f"(c[1]), "+f"(c[2]), "+f"(c[3])
        : "r"(a[0]), "r"(a[1]), "r"(a[2]), "r"(a[3]), "r"(b[0]), "r"(b[1]));
}

// ---------------------------------------------------------------------------
// Kernel 1: fused node-MLP GEMM on tensor cores (bf16 split, fp32 accum).
// Grid: x = 64 node-tiles (4 nodes each), y = 64 batch-tiles (128 rows each).
// ---------------------------------------------------------------------------
__global__ __launch_bounds__(256, 1)
void sdt_mma_kernel(const float* __restrict__ b1,
                    const float* __restrict__ w2,
                    const float* __restrict__ b2,
                    float* __restrict__ node_out /* [BATCH, 255] */) {
    extern __shared__ char smem[];
    const uint32_t smem_base = (uint32_t)__cvta_generic_to_shared(smem);

    const int tid   = threadIdx.x;
    const int lane  = tid & 31;
    const int warp  = tid >> 5;
    const int wm    = warp & 3;        // 0..3 -> 32-row slice
    const int wn    = warp >> 2;       // 0..1 -> 128-col slice
    const int mbase = blockIdx.y * BM;
    const int nbase = blockIdx.x * BN; // row index into padded w1 (node*64+h)

    float acc[2][16][4];
#pragma unroll
    for (int mt = 0; mt < 2; mt++)
#pragma unroll
        for (int nt = 0; nt < 16; nt++)
#pragma unroll
            for (int e = 0; e < 4; e++) acc[mt][nt][e] = 0.0f;

    // ---- cp.async tile loader for stage `st` into buffer `buf` ----
    auto issue_loads = [&](int st, int buf) {
        const int k0 = st * BK;
        const uint32_t base = smem_base + buf * BUF_STRIDE;
        // A: 128 rows x 4 chunks = 512 chunks, 2 per thread (x hi & lo)
#pragma unroll
        for (int i = 0; i < 2; i++) {
            int cid = tid + i * 256;
            int row = cid >> 2, c = cid & 3;
            int sw  = c ^ ((row >> 1) & 3);
            uint32_t soff = row * 64 + sw * 16;
            size_t g = (size_t)(mbase + row) * INPUT_DIM + k0 + c * 8;
            cp_async16(base + OFF_AH + soff, g_xh + g);
            cp_async16(base + OFF_AL + soff, g_xl + g);
        }
        // B: 256 rows x 4 chunks = 1024 chunks, 4 per thread (w1 hi & lo)
#pragma unroll
        for (int i = 0; i < 4; i++) {
            int cid = tid + i * 256;
            int row = cid >> 2, c = cid & 3;
            int sw  = c ^ ((row >> 1) & 3);
            uint32_t soff = row * 64 + sw * 16;
            size_t g = (size_t)(nbase + row) * INPUT_DIM + k0 + c * 8;
            cp_async16(base + OFF_BH + soff, g_w1h + g);
            cp_async16(base + OFF_BL + soff, g_w1l + g);
        }
    };

    issue_loads(0, 0);
    cp_commit();

    for (int st = 0; st < NSTAGES; st++) {
        const int cur = st & 1;
        if (st + 1 < NSTAGES) issue_loads(st + 1, cur ^ 1);
        cp_commit();
        cp_wait1();
        __syncthreads();

        const uint32_t base = smem_base + cur * BUF_STRIDE;
#pragma unroll
        for (int s = 0; s < 2; s++) {       // two k16 steps per stage
            uint32_t ah[2][4], al[2][4];
#pragma unroll
            for (int mt = 0; mt < 2; mt++) {
                int row   = wm * 32 + mt * 16 + (lane & 15);
                int chunk = 2 * s + (lane >> 4);
                int sw    = chunk ^ ((row >> 1) & 3);
                uint32_t addr = base + OFF_AH + row * 64 + sw * 16;
                ldsm_x4(ah[mt], addr);
                ldsm_x4(al[mt], addr + (OFF_AL - OFF_AH));
            }
#pragma unroll
            for (int nt2 = 0; nt2 < 8; nt2++) {
                int row   = wn * 128 + nt2 * 16 + (lane & 7) + ((lane >> 4) << 3);
                int chunk = 2 * s + ((lane >> 3) & 1);
                int sw    = chunk ^ ((row >> 1) & 3);
                uint32_t addr = base + OFF_BH + row * 64 + sw * 16;
                uint32_t bh[4], bl[4];
                ldsm_x4(bh, addr);
                ldsm_x4(bl, addr + (OFF_BL - OFF_BH));
#pragma unroll
                for (int mt = 0; mt < 2; mt++) {
#pragma unroll
                    for (int j = 0; j < 2; j++) {
                        float* c = acc[mt][nt2 * 2 + j];
                        mma_bf16(c, ah[mt], bh + j * 2);  // hi*hi
                        mma_bf16(c, ah[mt], bl + j * 2);  // hi*lo
                        mma_bf16(c, al[mt], bh + j * 2);  // lo*hi
                    }
                }
            }
        }
        __syncthreads();
    }

    // ---- Fused epilogue: bias -> relu -> dot w2 -> sigmoid -> node_out ----
    // Each (node, row) is owned by exactly one warp; reduce over lane&3 only.
#pragma unroll
    for (int nd = 0; nd < 2; nd++) {
        const int node = blockIdx.x * 4 + wn * 2 + nd;
        if (node >= NUM_INNER) continue;
        float b1v[16], w2v[16];
#pragma unroll
        for (int t = 0; t < 8; t++) {
#pragma unroll
            for (int e = 0; e < 2; e++) {
                int col = t * 8 + (lane & 3) * 2 + e;
                b1v[t * 2 + e] = b1[node * HIDDEN + col];
                w2v[t * 2 + e] = w2[node * HIDDEN + col];
            }
        }
        const float b2v = b2[node];
#pragma unroll
        for (int mt = 0; mt < 2; mt++) {
#pragma unroll
            for (int h = 0; h < 2; h++) {
                float sum = 0.0f;
#pragma unroll
                for (int t = 0; t < 8; t++) {
                    int nt = nd * 8 + t;
#pragma unroll
                    for (int e = 0; e < 2; e++) {
                        float v = acc[mt][nt][h * 2 + e] + b1v[t * 2 + e];
                        v = fmaxf(v, 0.0f);
                        sum = fmaf(v, w2v[t * 2 + e], sum);
                    }
                }
                sum += __shfl_xor_sync(0xffffffffu, sum, 1);
                sum += __shfl_xor_sync(0xffffffffu, sum, 2);
                if ((lane & 3) == 0) {
                    int row = mbase + wm * 32 + mt * 16 + (lane >> 2) + h * 8;
                    float lg = sum + b2v;
                    float sg = 1.0f / (1.0f + __expf(-lg));
                    node_out[(size_t)row * NUM_INNER + node] = sg;
                }
            }
        }
    }
}

// ---------------------------------------------------------------------------
// Kernel 2: tree traversal (unchanged; ~29us, memory-bound on 25MB writes)
// ---------------------------------------------------------------------------
__global__ __launch_bounds__(256)
void sdt_tree_kernel(const float* __restrict__ node_out,
                     const float* __restrict__ leaf,
                     float* __restrict__ h_out,
                     float* __restrict__ path_out,
                     float* __restrict__ reach_out) {
    const int b = blockIdx.x;
    const int t = threadIdx.x;

    __shared__ float p[NUM_INNER];
    __shared__ float red[8];

    if (t < NUM_INNER) p[t] = node_out[(size_t)b * NUM_INNER + t];
    __syncthreads();

    float prob = 1.0f;
#pragma unroll
    for (int v = 0; v < DEPTH; v++) {
        int node = (1 << v) - 1 + (t >> (DEPTH - v));
        float pv = p[node];
        prob *= ((t >> (DEPTH - 1 - v)) & 1) ? pv : (1.0f - pv);
    }
    path_out[(size_t)b * NUM_LEAVES + t] = prob;

    if (t < NUM_INNER) {
        int v = 31 - __clz(t + 1);
        int i = t + 1 - (1 << v);
        float reach = 1.0f;
        for (int u = 0; u < v; u++) {
            int node = (1 << u) - 1 + (i >> (v - u));
            float pv = p[node];
            reach *= ((i >> (v - 1 - u)) & 1) ? pv : (1.0f - pv);
        }
        reach_out[(size_t)b * NUM_INNER + t] = reach;
    }

    float contrib = prob * leaf[t];
#pragma unroll
    for (int off = 16; off; off >>= 1)
        contrib += __shfl_xor_sync(0xffffffffu, contrib, off);
    if ((t & 31) == 0) red[t >> 5] = contrib;
    __syncthreads();
    if (t < 8) {
        float v2 = red[t];
#pragma unroll
        for (int off = 4; off; off >>= 1)
            v2 += __shfl_xor_sync(0xffu, v2, off);
        if (t == 0) h_out[b] = v2;
    }
}

// ---------------------------------------------------------------------------
// Launch. d_in: x, w1, b1, w2, b2, leaf.
// d_out: [h_out | path_probs | node_outputs | node_reach]
// ---------------------------------------------------------------------------
extern "C" void kernel_launch(void* const* d_in, const int* in_sizes, int n_in,
                              void* d_out, int out_size) {
    const float* x    = (const float*)d_in[0];
    const float* w1   = (const float*)d_in[1];
    const float* b1   = (const float*)d_in[2];
    const float* w2   = (const float*)d_in[3];
    const float* b2   = (const float*)d_in[4];
    const float* leaf = (const float*)d_in[5];

    float* out       = (float*)d_out;
    float* h_out     = out;
    float* path_out  = out + BATCH;
    float* node_out  = out + BATCH + (size_t)BATCH * NUM_LEAVES;
    float* reach_out = node_out + (size_t)BATCH * NUM_INNER;

    sdt_prep_kernel<<<2048, 256>>>(x, w1);

    static bool attr_set = false;
    if (!attr_set) {
        cudaFuncSetAttribute(sdt_mma_kernel,
                             cudaFuncAttributeMaxDynamicSharedMemorySize, 98304);
        attr_set = true;
    }
    dim3 grid(BN == 256 ? NODES_PAD / 4 : 64, BATCH / BM);  // 64 x 64
    sdt_mma_kernel<<<grid, 256, 98304>>>(b1, w2, b2, node_out);

    sdt_tree_kernel<<<BATCH, 256>>>(node_out, leaf, h_out, path_out, reach_out);
}

// round 5
// speedup vs baseline: 15.8606x; 2.9140x over previous
#include <cuda_runtime.h>
#include <cuda_fp16.h>
#include <math.h>
#include <stdint.h>

// Problem constants
#define BATCH      8192
#define INPUT_DIM  256
#define HIDDEN     64
#define NUM_INNER  255
#define NUM_LEAVES 256
#define DEPTH      8

#define NODES_PAD  256
#define NX   (BATCH * INPUT_DIM)
#define NW1  (NUM_INNER * HIDDEN * INPUT_DIM)
#define NW1P (NODES_PAD * HIDDEN * INPUT_DIM)

// GEMM tiling: CTA = 128 rows x 128 cols (2 nodes), K in BK=32 stages
#define BM 128
#define BN 128
#define BK 32
#define NSTAGES (INPUT_DIM / BK)   // 8

// fp16 operand scratch (static device arrays; no allocation)
__device__ __half g_xh[NX];
__device__ __half g_w1h[NW1P];

// ---------------------------------------------------------------------------
// Prep: fp32 -> fp16 (x fits fp16 range: |x| < ~6; |w1| <= 0.14).
// Zero-pads w1 rows for node 255.
// ---------------------------------------------------------------------------
__global__ void sdt_prep_kernel(const float* __restrict__ x,
                                const float* __restrict__ w1) {
    int stride = gridDim.x * blockDim.x;
    for (int i = blockIdx.x * blockDim.x + threadIdx.x; i < NX; i += stride)
        g_xh[i] = __float2half_rn(x[i]);
    for (int i = blockIdx.x * blockDim.x + threadIdx.x; i < NW1P; i += stride)
        g_w1h[i] = __float2half_rn(i < NW1 ? w1[i] : 0.0f);
}

// ---------------------------------------------------------------------------
// smem: 2 stage buffers of (A 8KB | B 8KB). Rows 64B (32 halves);
// 16B chunk c stored at c ^ ((row>>1)&3).
// ---------------------------------------------------------------------------
#define OFF_A 0
#define OFF_B 8192
#define BUF_STRIDE 16384
#define SMEM_TOTAL (2 * BUF_STRIDE)   // 32768

__device__ __forceinline__ void cp_async16(uint32_t saddr, const void* gaddr) {
    asm volatile("cp.async.cg.shared.global [%0], [%1], 16;\n"
                 :: "r"(saddr), "l"(gaddr) : "memory");
}
__device__ __forceinline__ void cp_commit() {
    asm volatile("cp.async.commit_group;\n" ::: "memory");
}
__device__ __forceinline__ void cp_wait1() {
    asm volatile("cp.async.wait_group 1;\n" ::: "memory");
}
__device__ __forceinline__ void ldsm_x4(uint32_t* r, uint32_t addr) {
    asm volatile("ldmatrix.sync.aligned.m8n8.x4.shared.b16 {%0,%1,%2,%3}, [%4];\n"
                 : "=r"(r[0]), "=r"(r[1]), "=r"(r[2]), "=r"(r[3])
                 : "r"(addr));
}
__device__ __forceinline__ void mma_fp16(float* c, const uint32_t* a, const uint32_t* b) {
    asm volatile(
        "mma.sync.aligned.m16n8k16.row.col.f32.f16.f16.f32 "
        "{%0,%1,%2,%3}, {%4,%5,%6,%7}, {%8,%9}, {%0,%1,%2,%3};\n"
        : "+f"(c[0]), "+f"(c[1]), "+f"(c[2]), "+f"(c[3])
        : "r"(a[0]), "r"(a[1]), "r"(a[2]), "r"(a[3]), "r"(b[0]), "r"(b[1]));
}

// ---------------------------------------------------------------------------
// Kernel 1: fused node-MLP GEMM (fp16 operands, fp32 accum).
// Grid: x = 128 node-tiles (2 nodes each), y = 64 batch-tiles.
// 256 threads = 8 warps: wm = warp&3 (32-row slice), wn = warp>>2 (node).
// Each warp: 32m x 64n warp tile -> acc[2][8][4] = 64 regs.
// ---------------------------------------------------------------------------
__global__ __launch_bounds__(256, 2)
void sdt_mma_kernel(const float* __restrict__ b1,
                    const float* __restrict__ w2,
                    const float* __restrict__ b2,
                    float* __restrict__ node_out /* [BATCH, 255] */) {
    extern __shared__ char smem[];
    const uint32_t smem_base = (uint32_t)__cvta_generic_to_shared(smem);

    const int tid   = threadIdx.x;
    const int lane  = tid & 31;
    const int warp  = tid >> 5;
    const int wm    = warp & 3;        // 32-row slice
    const int wn    = warp >> 2;       // 0..1 -> which node (64 cols)
    const int mbase = blockIdx.y * BM;
    const int nbase = blockIdx.x * BN; // padded w1 row (node*64 + h)

    float acc[2][8][4];
#pragma unroll
    for (int mt = 0; mt < 2; mt++)
#pragma unroll
        for (int nt = 0; nt < 8; nt++)
#pragma unroll
            for (int e = 0; e < 4; e++) acc[mt][nt][e] = 0.0f;

    // ---- stage loader: A 512 chunks + B 512 chunks, 4 per thread ----
    auto issue_loads = [&](int st, int buf) {
        const int k0 = st * BK;
        const uint32_t base = smem_base + buf * BUF_STRIDE;
#pragma unroll
        for (int i = 0; i < 2; i++) {
            int cid = tid + i * 256;
            int row = cid >> 2, c = cid & 3;
            int sw  = c ^ ((row >> 1) & 3);
            uint32_t soff = row * 64 + sw * 16;
            cp_async16(base + OFF_A + soff,
                       g_xh + (size_t)(mbase + row) * INPUT_DIM + k0 + c * 8);
        }
#pragma unroll
        for (int i = 0; i < 2; i++) {
            int cid = tid + i * 256;
            int row = cid >> 2, c = cid & 3;
            int sw  = c ^ ((row >> 1) & 3);
            uint32_t soff = row * 64 + sw * 16;
            cp_async16(base + OFF_B + soff,
                       g_w1h + (size_t)(nbase + row) * INPUT_DIM + k0 + c * 8);
        }
    };

    issue_loads(0, 0);
    cp_commit();

    for (int st = 0; st < NSTAGES; st++) {
        const int cur = st & 1;
        if (st + 1 < NSTAGES) issue_loads(st + 1, cur ^ 1);
        cp_commit();
        cp_wait1();
        __syncthreads();

        const uint32_t base = smem_base + cur * BUF_STRIDE;
#pragma unroll
        for (int s = 0; s < 2; s++) {       // two k16 steps per stage
            uint32_t ah[2][4];
#pragma unroll
            for (int mt = 0; mt < 2; mt++) {
                int row   = wm * 32 + mt * 16 + (lane & 15);
                int chunk = 2 * s + (lane >> 4);
                int sw    = chunk ^ ((row >> 1) & 3);
                ldsm_x4(ah[mt], base + OFF_A + row * 64 + sw * 16);
            }
#pragma unroll
            for (int nt2 = 0; nt2 < 4; nt2++) {
                int row   = wn * 64 + nt2 * 16 + (lane & 7) + ((lane >> 4) << 3);
                int chunk = 2 * s + ((lane >> 3) & 1);
                int sw    = chunk ^ ((row >> 1) & 3);
                uint32_t bh[4];
                ldsm_x4(bh, base + OFF_B + row * 64 + sw * 16);
#pragma unroll
                for (int mt = 0; mt < 2; mt++) {
#pragma unroll
                    for (int j = 0; j < 2; j++)
                        mma_fp16(acc[mt][nt2 * 2 + j], ah[mt], bh + j * 2);
                }
            }
        }
        __syncthreads();
    }

    // ---- Fused epilogue: bias -> relu -> dot w2 -> sigmoid -> node_out ----
    // Warp wn owns node (blockIdx.x*2 + wn); reduce over lane&3 only.
    const int node = blockIdx.x * 2 + wn;
    if (node < NUM_INNER) {
        float b1v[16], w2v[16];
#pragma unroll
        for (int t = 0; t < 8; t++) {
#pragma unroll
            for (int e = 0; e < 2; e++) {
                int col = t * 8 + (lane & 3) * 2 + e;
                b1v[t * 2 + e] = b1[node * HIDDEN + col];
                w2v[t * 2 + e] = w2[node * HIDDEN + col];
            }
        }
        const float b2v = b2[node];
#pragma unroll
        for (int mt = 0; mt < 2; mt++) {
#pragma unroll
            for (int h = 0; h < 2; h++) {
                float sum = 0.0f;
#pragma unroll
                for (int t = 0; t < 8; t++) {
#pragma unroll
                    for (int e = 0; e < 2; e++) {
                        float v = acc[mt][t][h * 2 + e] + b1v[t * 2 + e];
                        v = fmaxf(v, 0.0f);
                        sum = fmaf(v, w2v[t * 2 + e], sum);
                    }
                }
                sum += __shfl_xor_sync(0xffffffffu, sum, 1);
                sum += __shfl_xor_sync(0xffffffffu, sum, 2);
                if ((lane & 3) == 0) {
                    int row = mbase + wm * 32 + mt * 16 + (lane >> 2) + h * 8;
                    float lg = sum + b2v;
                    float sg = 1.0f / (1.0f + __expf(-lg));
                    node_out[(size_t)row * NUM_INNER + node] = sg;
                }
            }
        }
    }
}

// ---------------------------------------------------------------------------
// Kernel 2: tree traversal. Leftmost descendant leaf writes each node's reach.
// ---------------------------------------------------------------------------
__global__ __launch_bounds__(256)
void sdt_tree_kernel(const float* __restrict__ node_out,
                     const float* __restrict__ leaf,
                     float* __restrict__ h_out,
                     float* __restrict__ path_out,
                     float* __restrict__ reach_out) {
    const int b = blockIdx.x;
    const int t = threadIdx.x;

    __shared__ float p[NUM_INNER];
    __shared__ float red[8];

    if (t < NUM_INNER) p[t] = node_out[(size_t)b * NUM_INNER + t];
    __syncthreads();

    float prob = 1.0f;
#pragma unroll
    for (int v = 0; v < DEPTH; v++) {
        int node = (1 << v) - 1 + (t >> (DEPTH - v));
        if ((t & ((1 << (DEPTH - v)) - 1)) == 0)
            reach_out[(size_t)b * NUM_INNER + node] = prob;
        float pv = p[node];
        prob *= ((t >> (DEPTH - 1 - v)) & 1) ? pv : (1.0f - pv);
    }
    path_out[(size_t)b * NUM_LEAVES + t] = prob;

    float contrib = prob * leaf[t];
#pragma unroll
    for (int off = 16; off; off >>= 1)
        contrib += __shfl_xor_sync(0xffffffffu, contrib, off);
    if ((t & 31) == 0) red[t >> 5] = contrib;
    __syncthreads();
    if (t < 8) {
        float v2 = red[t];
#pragma unroll
        for (int off = 4; off; off >>= 1)
            v2 += __shfl_xor_sync(0xffu, v2, off);
        if (t == 0) h_out[b] = v2;
    }
}

// ---------------------------------------------------------------------------
// Launch. d_in: x, w1, b1, w2, b2, leaf.
// d_out: [h_out | path_probs | node_outputs | node_reach]
// ---------------------------------------------------------------------------
extern "C" void kernel_launch(void* const* d_in, const int* in_sizes, int n_in,
                              void* d_out, int out_size) {
    const float* x    = (const float*)d_in[0];
    const float* w1   = (const float*)d_in[1];
    const float* b1   = (const float*)d_in[2];
    const float* w2   = (const float*)d_in[3];
    const float* b2   = (const float*)d_in[4];
    const float* leaf = (const float*)d_in[5];

    float* out       = (float*)d_out;
    float* h_out     = out;
    float* path_out  = out + BATCH;
    float* node_out  = out + BATCH + (size_t)BATCH * NUM_LEAVES;
    float* reach_out = node_out + (size_t)BATCH * NUM_INNER;

    sdt_prep_kernel<<<2048, 256>>>(x, w1);

    dim3 grid(NODES_PAD / 2, BATCH / BM);   // 128 x 64
    sdt_mma_kernel<<<grid, 256, SMEM_TOTAL>>>(b1, w2, b2, node_out);

    sdt_tree_kernel<<<BATCH, 256>>>(node_out, leaf, h_out, path_out, reach_out);
}